// round 12
// baseline (speedup 1.0000x reference)
#include <cuda_runtime.h>
#include <cuda_fp16.h>

// Shape: B = 65536 rows, C = 1000 fp32 classes. 250 float4 per row.
#define NCLS    1000
#define TPB     32
#define MAXGRID 8192

__device__ double   g_part[MAXGRID];
__device__ unsigned g_ticket = 0;

__device__ __forceinline__ float warp_sum(float v) {
    #pragma unroll
    for (int o = 16; o > 0; o >>= 1) v += __shfl_xor_sync(0xffffffffu, v, o);
    return v;
}
__device__ __forceinline__ double warp_sum_d(double v) {
    #pragma unroll
    for (int o = 16; o > 0; o >>= 1) v += __shfl_xor_sync(0xffffffffu, v, o);
    return v;
}

__global__ void __launch_bounds__(TPB, 28)
mvce_warp(const float* __restrict__ outp, const float* __restrict__ tgt,
          float* __restrict__ result, int B, int nwarps) {
    const int lane = threadIdx.x;
    const int gw   = blockIdx.x;

    double acc = 0.0;

    for (int row = gw; row < B; row += nwarps) {
        const float4* __restrict__ o4 =
            reinterpret_cast<const float4*>(outp + (size_t)row * NCLS);
        const float4* __restrict__ t4 =
            reinterpret_cast<const float4*>(tgt  + (size_t)row * NCLS);

        // Compressed register-resident row: e=exp(o) and masked t, as half2.
        // th stores t for positives, 0 for negatives (class decided in fp32).
        __half2 eh[16], th[16];
        float s = 0.f, tn = 0.f, an = 0.f, ap = 0.f, np = 0.f;

        #pragma unroll
        for (int k = 0; k < 8; k++) {
            const int  idx   = k * 32 + lane;
            const bool valid = (k < 7) || (lane < 26);   // 250 float4/row
            float4 ov = valid ? o4[idx] : make_float4(0.f, 0.f, 0.f, 0.f);
            float4 tv = valid ? t4[idx] : make_float4(0.f, 0.f, 0.f, 0.f);
            float4 e;
            e.x = valid ? __expf(ov.x) : 0.f;
            e.y = valid ? __expf(ov.y) : 0.f;
            e.z = valid ? __expf(ov.z) : 0.f;
            e.w = valid ? __expf(ov.w) : 0.f;

            float tm[4];
            {   // per-element pass-A accumulate (predicated, no divergence cost)
                float ee[4] = {e.x, e.y, e.z, e.w};
                float tt[4] = {tv.x, tv.y, tv.z, tv.w};
                float oo[4] = {ov.x, ov.y, ov.z, ov.w};
                #pragma unroll
                for (int j = 0; j < 4; j++) {
                    float to = tt[j] * oo[j];
                    if (tt[j] > 0.5f) {           // positive
                        ap += to;
                        np += 1.0f;
                        tm[j] = tt[j];
                    } else {                       // negative (incl. padded tail)
                        s  += ee[j];
                        tn += tt[j];
                        an += to;
                        tm[j] = 0.0f;
                    }
                }
            }
            eh[2 * k]     = __floats2half2_rn(e.x, e.y);
            eh[2 * k + 1] = __floats2half2_rn(e.z, e.w);
            th[2 * k]     = __floats2half2_rn(tm[0], tm[1]);
            th[2 * k + 1] = __floats2half2_rn(tm[2], tm[3]);
        }

        // ---- warp butterflies (all lanes get totals, no barriers) ----
        const float Sneg = warp_sum(s);
        const float Tneg = warp_sum(tn);
        const float Aneg = warp_sum(an);

        // ---- pass B: sum over positives of (Tneg + t_p) * log(Sneg + e_p) ----
        float L = 0.f;
        #pragma unroll
        for (int i = 0; i < 16; i++) {
            float2 e2 = __half22float2(eh[i]);
            float2 t2 = __half22float2(th[i]);
            if (t2.x > 0.25f) L = fmaf(Tneg + t2.x, __logf(Sneg + e2.x), L);
            if (t2.y > 0.25f) L = fmaf(Tneg + t2.y, __logf(Sneg + e2.y), L);
        }

        const float Lt  = warp_sum(L);
        const float apT = warp_sum(ap);
        const float npT = warp_sum(np);

        float r;
        if (npT > 0.0f) {
            r = (Lt - npT * Aneg - apT) / npT;
        } else {
            r = Tneg * __logf(Sneg) - Aneg;   // no-positive fallback
        }
        acc += (double)r;
    }

    // ---- per-warp partial + fused deterministic fan-in ----
    if (lane == 0) g_part[gw] = acc;

    unsigned isLast = 0;
    if (lane == 0) {
        __threadfence();
        if (atomicAdd(&g_ticket, 1u) == (unsigned)(gridDim.x - 1)) isLast = 1;
    }
    isLast = __shfl_sync(0xffffffffu, isLast, 0);

    if (isLast) {
        __threadfence();                       // see all partials
        const int n = gridDim.x;
        double a = 0.0;
        for (int i = lane; i < n; i += 32)     // fixed order -> deterministic
            a += g_part[i];
        a = warp_sum_d(a);
        if (lane == 0) {
            result[0] = (float)(a / (double)B);
            g_ticket = 0;                      // reset for next graph replay
        }
    }
}

extern "C" void kernel_launch(void* const* d_in, const int* in_sizes, int n_in,
                              void* d_out, int out_size) {
    const float* output = (const float*)d_in[0];
    const float* target = (const float*)d_in[1];
    float* out = (float*)d_out;

    const int B = in_sizes[0] / NCLS;

    int grid = 148 * 32;             // one warp-CTA per slot, ~14 rows each
    if (grid > B) grid = B;
    if (grid > MAXGRID) grid = MAXGRID;
    if (grid < 1) grid = 1;

    mvce_warp<<<grid, TPB>>>(output, target, out, B, grid);
}